// round 5
// baseline (speedup 1.0000x reference)
#include <cuda_runtime.h>
#include <cuda_fp16.h>

#define VOCAB 30000
#define DIM   768
#define SEQL  512
#define HWORDS (VOCAB / 2)   // packed 16-bit counts, 2 per u32
#define ROW4  (DIM / 8)      // 96 uint4 (8 halves) per Wt row

// Scratch: transposed weights Wt[VOCAB][DIM] (fp16, 46 MB). Device global
// per the allocation rules (no cudaMalloc anywhere).
__device__ __half g_Wt[(size_t)VOCAB * DIM];

// ---------------------------------------------------------------------------
// Transpose W [DIM, VOCAB] (row-major fp32) -> g_Wt [VOCAB, DIM] (fp16)
// ---------------------------------------------------------------------------
__global__ void transpose_kernel(const float* __restrict__ W) {
    __shared__ float tile[32][33];
    int t0 = blockIdx.x * 32;   // vocab tile base
    int d0 = blockIdx.y * 32;   // dim tile base
    int x = threadIdx.x;        // 0..31
    int y = threadIdx.y;        // 0..7

#pragma unroll
    for (int i = 0; i < 32; i += 8) {
        int d = d0 + y + i;
        int t = t0 + x;
        if (t < VOCAB)  // d < DIM guaranteed (DIM % 32 == 0)
            tile[y + i][x] = W[(size_t)d * VOCAB + t];
    }
    __syncthreads();
#pragma unroll
    for (int i = 0; i < 32; i += 8) {
        int t = t0 + y + i;
        int d = d0 + x;
        if (t < VOCAB)
            g_Wt[(size_t)t * DIM + d] = __float2half_rn(tile[x][y + i]);
    }
}

// ---------------------------------------------------------------------------
// Main kernel: one CTA per document row.
//  Phase 1: validity + doc_len (syncthreads_count)
//  Phase 2: packed 16-bit histogram in smem (tf counts)
//  Phase 3: dedup (atomicAnd fetch-and-clear) + BM25 score per unique token
//  Phase 4: warp-per-token LDG.128 gather, fp32 accumulate, atomic smem reduce
//  Phase 5: L2 normalize, write out
// ---------------------------------------------------------------------------
// smem layout (u32 words): hist[15000] | redbuf[768] | combo[1024] | warpsum[16]
#define SMEM_WORDS (HWORDS + DIM + 2 * SEQL + 16)
#define SMEM_BYTES (SMEM_WORDS * 4)

__global__ __launch_bounds__(512, 2)
void bm25_kernel(const int* __restrict__ ids,
                 const int* __restrict__ mask,
                 float* __restrict__ out) {
    extern __shared__ unsigned int sm[];
    unsigned int*       hist    = sm;                              // HWORDS
    float*              redbuf  = (float*)(sm + HWORDS);           // DIM
    unsigned long long* combo   = (unsigned long long*)(redbuf + DIM); // SEQL (8B each)
    float*              warpsum = (float*)(combo + SEQL);          // 16

    const int tid = threadIdx.x;
    const int b   = blockIdx.x;

    // ---- Phase 1: load token, validity ----
    int id = ids [(size_t)b * SEQL + tid];
    int mk = mask[(size_t)b * SEQL + tid];
    bool valid = (mk == 1) && (id > 100) && (id < VOCAB);
    int  t = valid ? id : 0;

    // zero histogram + reduction buffer (completes before the barrier below)
#pragma unroll
    for (int i = tid; i < HWORDS; i += 512) hist[i] = 0u;
    for (int i = tid; i < DIM;    i += 512) redbuf[i] = 0.0f;

    int doc_len = __syncthreads_count(valid);   // barrier + valid count

    // ---- Phase 2: histogram (tf with multiplicity) ----
    const unsigned sh = ((unsigned)t & 1u) << 4;
    if (valid) atomicAdd(&hist[t >> 1], 1u << sh);
    __syncthreads();

    // ---- Phase 3: dedup + score ----
    float length_norm = fmaxf(1.0f + 0.75f * ((float)doc_len * 0.01f - 1.0f), 0.5f);
    float s = 0.0f;
    if (valid) {
        unsigned old = atomicAnd(&hist[t >> 1], ~(0xFFFFu << sh));
        unsigned cnt = (old >> sh) & 0xFFFFu;
        if (cnt) {
            float tf = (float)cnt;
            s = tf * 2.2f / (tf + 1.2f * length_norm);   // (K1+1)=2.2, K1=1.2
        }
    }
    // pack (score, token) for one LDS.64 broadcast in phase 4
    combo[tid] = ((unsigned long long)__float_as_uint(s) << 32) | (unsigned)t;
    __syncthreads();

    // ---- Phase 4: warp-per-token gather (LDG.128), fp32 accumulate ----
    // Warp w handles tokens j = w, w+16, ... Lane l covers dims
    // {seg*256 + l*8 .. +8} for seg = 0..2  (3x uint4 = 24 halves per token).
    const int wid  = tid >> 5;
    const int lane = tid & 31;
    const uint4* __restrict__ Wt4 = (const uint4*)g_Wt;

    float acc[3][8];
#pragma unroll
    for (int sgi = 0; sgi < 3; sgi++)
#pragma unroll
        for (int k = 0; k < 8; k++) acc[sgi][k] = 0.0f;

    for (int j = wid; j < SEQL; j += 16) {
        unsigned long long cb = combo[j];
        float sj = __uint_as_float((unsigned)(cb >> 32));
        int   tj = (int)(unsigned)cb;
        size_t base = (size_t)tj * ROW4 + lane;
        uint4 u0 = __ldg(Wt4 + base);
        uint4 u1 = __ldg(Wt4 + base + 32);
        uint4 u2 = __ldg(Wt4 + base + 64);
        const __half2* h0 = (const __half2*)&u0;
        const __half2* h1 = (const __half2*)&u1;
        const __half2* h2 = (const __half2*)&u2;
#pragma unroll
        for (int q = 0; q < 4; q++) {
            float2 f0 = __half22float2(h0[q]);
            float2 f1 = __half22float2(h1[q]);
            float2 f2 = __half22float2(h2[q]);
            acc[0][2*q]   = fmaf(sj, f0.x, acc[0][2*q]);
            acc[0][2*q+1] = fmaf(sj, f0.y, acc[0][2*q+1]);
            acc[1][2*q]   = fmaf(sj, f1.x, acc[1][2*q]);
            acc[1][2*q+1] = fmaf(sj, f1.y, acc[1][2*q+1]);
            acc[2][2*q]   = fmaf(sj, f2.x, acc[2][2*q]);
            acc[2][2*q+1] = fmaf(sj, f2.y, acc[2][2*q+1]);
        }
    }
#pragma unroll
    for (int sgi = 0; sgi < 3; sgi++)
#pragma unroll
        for (int k = 0; k < 8; k++)
            atomicAdd(&redbuf[sgi * 256 + lane * 8 + k], acc[sgi][k]);
    __syncthreads();

    // ---- Phase 5: normalize + write ----
    float p = 0.0f;
    for (int d = tid; d < DIM; d += 512) { float v = redbuf[d]; p = fmaf(v, v, p); }
#pragma unroll
    for (int o = 16; o; o >>= 1) p += __shfl_xor_sync(0xFFFFFFFFu, p, o);
    if ((tid & 31) == 0) warpsum[tid >> 5] = p;
    __syncthreads();
    if (tid == 0) {
        float ss = 0.0f;
#pragma unroll
        for (int w = 0; w < 16; w++) ss += warpsum[w];
        warpsum[0] = rsqrtf(fmaxf(ss, 1e-30f));
    }
    __syncthreads();
    float rn = warpsum[0];
    for (int d = tid; d < DIM; d += 512)
        out[(size_t)b * DIM + d] = redbuf[d] * rn;
}

// ---------------------------------------------------------------------------
extern "C" void kernel_launch(void* const* d_in, const int* in_sizes, int n_in,
                              void* d_out, int out_size) {
    const int*   ids  = (const int*)d_in[0];
    const int*   mask = (const int*)d_in[1];
    const float* W    = (const float*)d_in[2];
    float*       out  = (float*)d_out;

    int B = in_sizes[0] / SEQL;

    // W -> Wt (transposed, fp16) into the device-global scratch
    dim3 tb(32, 8);
    dim3 tg((VOCAB + 31) / 32, DIM / 32);
    transpose_kernel<<<tg, tb>>>(W);

    cudaFuncSetAttribute(bm25_kernel,
                         cudaFuncAttributeMaxDynamicSharedMemorySize, SMEM_BYTES);
    bm25_kernel<<<B, 512, SMEM_BYTES>>>(ids, mask, out);
}

// round 6
// speedup vs baseline: 1.0477x; 1.0477x over previous
#include <cuda_runtime.h>
#include <cuda_fp16.h>

#define VOCAB 30000
#define DIM   768
#define SEQL  512
#define HWORDS (VOCAB / 2)   // packed 16-bit counts, 2 per u32
#define ROWH2 (DIM / 2)      // 384 half2 per Wt row

// Scratch: transposed weights Wt[VOCAB][DIM] (fp16, 46 MB). Device global
// per the allocation rules (no cudaMalloc anywhere).
__device__ __half g_Wt[(size_t)VOCAB * DIM];

// ---------------------------------------------------------------------------
// Transpose W [DIM, VOCAB] (row-major fp32) -> g_Wt [VOCAB, DIM] (fp16)
// ---------------------------------------------------------------------------
__global__ void transpose_kernel(const float* __restrict__ W) {
    __shared__ float tile[32][33];
    int t0 = blockIdx.x * 32;   // vocab tile base
    int d0 = blockIdx.y * 32;   // dim tile base
    int x = threadIdx.x;        // 0..31
    int y = threadIdx.y;        // 0..7

#pragma unroll
    for (int i = 0; i < 32; i += 8) {
        int d = d0 + y + i;
        int t = t0 + x;
        if (t < VOCAB)  // d < DIM guaranteed (DIM % 32 == 0)
            tile[y + i][x] = W[(size_t)d * VOCAB + t];
    }
    __syncthreads();
#pragma unroll
    for (int i = 0; i < 32; i += 8) {
        int t = t0 + y + i;
        int d = d0 + x;
        if (t < VOCAB)
            g_Wt[(size_t)t * DIM + d] = __float2half_rn(tile[x][y + i]);
    }
}

// ---------------------------------------------------------------------------
// Main kernel: one CTA per document row.
//  Phase 1: validity + doc_len (syncthreads_count)
//  Phase 2: packed 16-bit histogram in smem (tf counts)
//  Phase 3: dedup (atomicAnd fetch-and-clear) + BM25 score, pack into combo
//  Phase 4: group-of-128 gather (LDG.32, coalesced), 2-token unroll, fp32 acc
//  Phase 5: L2 normalize, write out
// ---------------------------------------------------------------------------
// smem layout (u32 words): hist[15000] | redbuf[768] | combo[1024] | warpsum[16]
#define SMEM_WORDS (HWORDS + DIM + 2 * SEQL + 16)
#define SMEM_BYTES (SMEM_WORDS * 4)

__global__ __launch_bounds__(512, 3)
void bm25_kernel(const int* __restrict__ ids,
                 const int* __restrict__ mask,
                 float* __restrict__ out) {
    extern __shared__ unsigned int sm[];
    unsigned int*       hist    = sm;                                  // HWORDS
    float*              redbuf  = (float*)(sm + HWORDS);               // DIM
    unsigned long long* combo   = (unsigned long long*)(redbuf + DIM); // SEQL
    float*              warpsum = (float*)(combo + SEQL);              // 16

    const int tid = threadIdx.x;
    const int b   = blockIdx.x;

    // ---- Phase 1: load token, validity ----
    int id = ids [(size_t)b * SEQL + tid];
    int mk = mask[(size_t)b * SEQL + tid];
    bool valid = (mk == 1) && (id > 100) && (id < VOCAB);
    int  t = valid ? id : 0;

    // zero histogram + reduction buffer (completes before the barrier below)
#pragma unroll
    for (int i = tid; i < HWORDS; i += 512) hist[i] = 0u;
    for (int i = tid; i < DIM;    i += 512) redbuf[i] = 0.0f;

    int doc_len = __syncthreads_count(valid);   // barrier + valid count

    // ---- Phase 2: histogram (tf with multiplicity) ----
    const unsigned sh = ((unsigned)t & 1u) << 4;
    if (valid) atomicAdd(&hist[t >> 1], 1u << sh);
    __syncthreads();

    // ---- Phase 3: dedup + score ----
    float length_norm = fmaxf(1.0f + 0.75f * ((float)doc_len * 0.01f - 1.0f), 0.5f);
    float s = 0.0f;
    if (valid) {
        unsigned old = atomicAnd(&hist[t >> 1], ~(0xFFFFu << sh));
        unsigned cnt = (old >> sh) & 0xFFFFu;
        if (cnt) {
            float tf = (float)cnt;
            s = tf * 2.2f / (tf + 1.2f * length_norm);   // (K1+1)=2.2, K1=1.2
        }
    }
    // group-major combo layout: token tid -> slot (tid&3)*128 + (tid>>2)
    // so each gather group's tokens are contiguous (enables LDS.128 pairs)
    combo[(tid & 3) * 128 + (tid >> 2)] =
        ((unsigned long long)__float_as_uint(s) << 32) | (unsigned)t;
    __syncthreads();

    // ---- Phase 4: gather-accumulate (fp16 weights, fp32 accum) ----
    // 4 token groups x 128 lanes. Lane l owns dims {2l,2l+1, 256+2l,256+2l+1,
    // 512+2l,512+2l+1} -> every LDG.32 is a fully-coalesced warp access.
    // 2 tokens per iteration: one LDS.128 combo read, 6 LDG.32 in flight.
    const int group = tid >> 7;        // 0..3
    const int lane  = tid & 127;       // 0..127
    const __half2* __restrict__ Wt2 = (const __half2*)g_Wt;
    const ulonglong2* __restrict__ cpair =
        (const ulonglong2*)(combo + group * 128);

    float a0x = 0.f, a0y = 0.f, a1x = 0.f, a1y = 0.f, a2x = 0.f, a2y = 0.f;
#pragma unroll 2
    for (int i = 0; i < 64; i++) {
        ulonglong2 cb = cpair[i];
        float sj0 = __uint_as_float((unsigned)(cb.x >> 32));
        int   tj0 = (int)(unsigned)cb.x;
        float sj1 = __uint_as_float((unsigned)(cb.y >> 32));
        int   tj1 = (int)(unsigned)cb.y;
        unsigned idx0 = (unsigned)tj0 * ROWH2 + lane;
        unsigned idx1 = (unsigned)tj1 * ROWH2 + lane;
        __half2 p0 = __ldg(&Wt2[idx0 +   0]);
        __half2 p1 = __ldg(&Wt2[idx0 + 128]);
        __half2 p2 = __ldg(&Wt2[idx0 + 256]);
        __half2 q0 = __ldg(&Wt2[idx1 +   0]);
        __half2 q1 = __ldg(&Wt2[idx1 + 128]);
        __half2 q2 = __ldg(&Wt2[idx1 + 256]);
        float2 f;
        f = __half22float2(p0); a0x = fmaf(sj0, f.x, a0x); a0y = fmaf(sj0, f.y, a0y);
        f = __half22float2(p1); a1x = fmaf(sj0, f.x, a1x); a1y = fmaf(sj0, f.y, a1y);
        f = __half22float2(p2); a2x = fmaf(sj0, f.x, a2x); a2y = fmaf(sj0, f.y, a2y);
        f = __half22float2(q0); a0x = fmaf(sj1, f.x, a0x); a0y = fmaf(sj1, f.y, a0y);
        f = __half22float2(q1); a1x = fmaf(sj1, f.x, a1x); a1y = fmaf(sj1, f.y, a1y);
        f = __half22float2(q2); a2x = fmaf(sj1, f.x, a2x); a2y = fmaf(sj1, f.y, a2y);
    }
    atomicAdd(&redbuf[      2 * lane    ], a0x);
    atomicAdd(&redbuf[      2 * lane + 1], a0y);
    atomicAdd(&redbuf[256 + 2 * lane    ], a1x);
    atomicAdd(&redbuf[256 + 2 * lane + 1], a1y);
    atomicAdd(&redbuf[512 + 2 * lane    ], a2x);
    atomicAdd(&redbuf[512 + 2 * lane + 1], a2y);
    __syncthreads();

    // ---- Phase 5: normalize + write ----
    float p = 0.0f;
    for (int d = tid; d < DIM; d += 512) { float v = redbuf[d]; p = fmaf(v, v, p); }
#pragma unroll
    for (int o = 16; o; o >>= 1) p += __shfl_xor_sync(0xFFFFFFFFu, p, o);
    if ((tid & 31) == 0) warpsum[tid >> 5] = p;
    __syncthreads();
    if (tid == 0) {
        float ss = 0.0f;
#pragma unroll
        for (int w = 0; w < 16; w++) ss += warpsum[w];
        warpsum[0] = rsqrtf(fmaxf(ss, 1e-30f));
    }
    __syncthreads();
    float rn = warpsum[0];
    for (int d = tid; d < DIM; d += 512)
        out[(size_t)b * DIM + d] = redbuf[d] * rn;
}

// ---------------------------------------------------------------------------
extern "C" void kernel_launch(void* const* d_in, const int* in_sizes, int n_in,
                              void* d_out, int out_size) {
    const int*   ids  = (const int*)d_in[0];
    const int*   mask = (const int*)d_in[1];
    const float* W    = (const float*)d_in[2];
    float*       out  = (float*)d_out;

    int B = in_sizes[0] / SEQL;

    // W -> Wt (transposed, fp16) into the device-global scratch
    dim3 tb(32, 8);
    dim3 tg((VOCAB + 31) / 32, DIM / 32);
    transpose_kernel<<<tg, tb>>>(W);

    cudaFuncSetAttribute(bm25_kernel,
                         cudaFuncAttributeMaxDynamicSharedMemorySize, SMEM_BYTES);
    bm25_kernel<<<B, 512, SMEM_BYTES>>>(ids, mask, out);
}

// round 7
// speedup vs baseline: 1.0517x; 1.0038x over previous
#include <cuda_runtime.h>
#include <cuda_fp16.h>

#define VOCAB 30000
#define DIM   768
#define SEQL  512
#define HWORDS (VOCAB / 2)   // packed 16-bit counts, 2 per u32
#define ROWH2 (DIM / 2)      // 384 half2 per Wt row

// Scratch: transposed weights Wt[VOCAB][DIM] (fp16, 46 MB). Device global
// per the allocation rules (no cudaMalloc anywhere).
__device__ __half g_Wt[(size_t)VOCAB * DIM];

// ---------------------------------------------------------------------------
// Transpose W [DIM, VOCAB] (row-major fp32) -> g_Wt [VOCAB, DIM] (fp16)
// ---------------------------------------------------------------------------
__global__ void transpose_kernel(const float* __restrict__ W) {
    __shared__ float tile[32][33];
    int t0 = blockIdx.x * 32;   // vocab tile base
    int d0 = blockIdx.y * 32;   // dim tile base
    int x = threadIdx.x;        // 0..31
    int y = threadIdx.y;        // 0..7

#pragma unroll
    for (int i = 0; i < 32; i += 8) {
        int d = d0 + y + i;
        int t = t0 + x;
        if (t < VOCAB)  // d < DIM guaranteed (DIM % 32 == 0)
            tile[y + i][x] = W[(size_t)d * VOCAB + t];
    }
    __syncthreads();
#pragma unroll
    for (int i = 0; i < 32; i += 8) {
        int t = t0 + y + i;
        int d = d0 + x;
        if (t < VOCAB)
            g_Wt[(size_t)t * DIM + d] = __float2half_rn(tile[x][y + i]);
    }
}

// ---------------------------------------------------------------------------
// Main kernel: one CTA per document row.  (R3 structure + FFMA2 + combo u64)
// ---------------------------------------------------------------------------
// smem layout (u32 words): hist[15000] | redbuf[768] | combo[1024] | warpsum[16]
#define SMEM_WORDS (HWORDS + DIM + 2 * SEQL + 16)
#define SMEM_BYTES (SMEM_WORDS * 4)

__global__ __launch_bounds__(512, 3)
void bm25_kernel(const int* __restrict__ ids,
                 const int* __restrict__ mask,
                 float* __restrict__ out) {
    extern __shared__ unsigned int sm[];
    unsigned int*       hist    = sm;                                  // HWORDS
    float*              redbuf  = (float*)(sm + HWORDS);               // DIM
    unsigned long long* combo   = (unsigned long long*)(redbuf + DIM); // SEQL
    float*              warpsum = (float*)(combo + SEQL);              // 16

    const int tid = threadIdx.x;
    const int b   = blockIdx.x;

    // ---- Phase 1: load token, validity ----
    int id = ids [(size_t)b * SEQL + tid];
    int mk = mask[(size_t)b * SEQL + tid];
    bool valid = (mk == 1) && (id > 100) && (id < VOCAB);
    int  t = valid ? id : 0;

    // zero histogram + reduction buffer (completes before the barrier below)
#pragma unroll
    for (int i = tid; i < HWORDS; i += 512) hist[i] = 0u;
    for (int i = tid; i < DIM;    i += 512) redbuf[i] = 0.0f;

    int doc_len = __syncthreads_count(valid);   // barrier + valid count

    // ---- Phase 2: histogram (tf with multiplicity) ----
    const unsigned sh = ((unsigned)t & 1u) << 4;
    if (valid) atomicAdd(&hist[t >> 1], 1u << sh);
    __syncthreads();

    // ---- Phase 3: dedup + score ----
    float length_norm = fmaxf(1.0f + 0.75f * ((float)doc_len * 0.01f - 1.0f), 0.5f);
    float s = 0.0f;
    if (valid) {
        unsigned old = atomicAnd(&hist[t >> 1], ~(0xFFFFu << sh));
        unsigned cnt = (old >> sh) & 0xFFFFu;
        if (cnt) {
            float tf = (float)cnt;
            s = tf * 2.2f / (tf + 1.2f * length_norm);   // (K1+1)=2.2, K1=1.2
        }
    }
    // pack (score, token) -> one LDS.64 broadcast per token in phase 4
    combo[tid] = ((unsigned long long)__float_as_uint(s) << 32) | (unsigned)t;
    __syncthreads();

    // ---- Phase 4: gather-accumulate (fp16 weights, packed f32x2 accum) ----
    // 4 token groups x 128 lanes. Lane l owns dims {2l,2l+1, 256+2l,256+2l+1,
    // 512+2l,512+2l+1} -> every LDG.32 is a fully-coalesced warp access.
    const int group = tid >> 7;        // 0..3
    const int lane  = tid & 127;       // 0..127
    const __half2* __restrict__ Wt2 = (const __half2*)g_Wt;

    unsigned long long a0 = 0ull, a1 = 0ull, a2 = 0ull;   // packed float2 accums
#pragma unroll 4
    for (int j = group; j < SEQL; j += 4) {
        unsigned long long cb = combo[j];
        float sj = __uint_as_float((unsigned)(cb >> 32));
        int   tj = (int)(unsigned)cb;
        unsigned long long s2;
        asm("mov.b64 %0, {%1, %1};" : "=l"(s2) : "f"(sj));
        unsigned idx = (unsigned)tj * ROWH2 + lane;
        __half2 h0 = __ldg(&Wt2[idx +   0]);
        __half2 h1 = __ldg(&Wt2[idx + 128]);
        __half2 h2 = __ldg(&Wt2[idx + 256]);
        float2 f0 = __half22float2(h0);
        float2 f1 = __half22float2(h1);
        float2 f2 = __half22float2(h2);
        unsigned long long w0, w1, w2;
        asm("mov.b64 %0, {%1, %2};" : "=l"(w0) : "f"(f0.x), "f"(f0.y));
        asm("mov.b64 %0, {%1, %2};" : "=l"(w1) : "f"(f1.x), "f"(f1.y));
        asm("mov.b64 %0, {%1, %2};" : "=l"(w2) : "f"(f2.x), "f"(f2.y));
        asm("fma.rn.f32x2 %0, %1, %2, %0;" : "+l"(a0) : "l"(w0), "l"(s2));
        asm("fma.rn.f32x2 %0, %1, %2, %0;" : "+l"(a1) : "l"(w1), "l"(s2));
        asm("fma.rn.f32x2 %0, %1, %2, %0;" : "+l"(a2) : "l"(w2), "l"(s2));
    }
    {
        float x0, y0, x1, y1, x2, y2;
        asm("mov.b64 {%0, %1}, %2;" : "=f"(x0), "=f"(y0) : "l"(a0));
        asm("mov.b64 {%0, %1}, %2;" : "=f"(x1), "=f"(y1) : "l"(a1));
        asm("mov.b64 {%0, %1}, %2;" : "=f"(x2), "=f"(y2) : "l"(a2));
        atomicAdd(&redbuf[      2 * lane    ], x0);
        atomicAdd(&redbuf[      2 * lane + 1], y0);
        atomicAdd(&redbuf[256 + 2 * lane    ], x1);
        atomicAdd(&redbuf[256 + 2 * lane + 1], y1);
        atomicAdd(&redbuf[512 + 2 * lane    ], x2);
        atomicAdd(&redbuf[512 + 2 * lane + 1], y2);
    }
    __syncthreads();

    // ---- Phase 5: normalize + write ----
    float p = 0.0f;
    for (int d = tid; d < DIM; d += 512) { float v = redbuf[d]; p = fmaf(v, v, p); }
#pragma unroll
    for (int o = 16; o; o >>= 1) p += __shfl_xor_sync(0xFFFFFFFFu, p, o);
    if ((tid & 31) == 0) warpsum[tid >> 5] = p;
    __syncthreads();
    if (tid == 0) {
        float ss = 0.0f;
#pragma unroll
        for (int w = 0; w < 16; w++) ss += warpsum[w];
        warpsum[0] = rsqrtf(fmaxf(ss, 1e-30f));
    }
    __syncthreads();
    float rn = warpsum[0];
    for (int d = tid; d < DIM; d += 512)
        out[(size_t)b * DIM + d] = redbuf[d] * rn;
}

// ---------------------------------------------------------------------------
extern "C" void kernel_launch(void* const* d_in, const int* in_sizes, int n_in,
                              void* d_out, int out_size) {
    const int*   ids  = (const int*)d_in[0];
    const int*   mask = (const int*)d_in[1];
    const float* W    = (const float*)d_in[2];
    float*       out  = (float*)d_out;

    int B = in_sizes[0] / SEQL;

    // W -> Wt (transposed, fp16) into the device-global scratch
    dim3 tb(32, 8);
    dim3 tg((VOCAB + 31) / 32, DIM / 32);
    transpose_kernel<<<tg, tb>>>(W);

    cudaFuncSetAttribute(bm25_kernel,
                         cudaFuncAttributeMaxDynamicSharedMemorySize, SMEM_BYTES);
    bm25_kernel<<<B, 512, SMEM_BYTES>>>(ids, mask, out);
}

// round 9
// speedup vs baseline: 1.0532x; 1.0014x over previous
#include <cuda_runtime.h>
#include <cuda_fp16.h>

#define VOCAB 30000
#define DIM   768
#define SEQL  512
#define HWORDS (VOCAB / 2)   // packed 16-bit counts, 2 per u32
#define ROWH2 (DIM / 2)      // 384 half2 per Wt row

// Scratch: transposed weights Wt[VOCAB][DIM] (fp16, 46 MB). Device global
// per the allocation rules (no cudaMalloc anywhere).
__device__ __half g_Wt[(size_t)VOCAB * DIM];

// ---------------------------------------------------------------------------
// Transpose W [DIM, VOCAB] (row-major fp32) -> g_Wt [VOCAB, DIM] (fp16)
// ---------------------------------------------------------------------------
__global__ void transpose_kernel(const float* __restrict__ W) {
    __shared__ float tile[32][33];
    int t0 = blockIdx.x * 32;   // vocab tile base
    int d0 = blockIdx.y * 32;   // dim tile base
    int x = threadIdx.x;        // 0..31
    int y = threadIdx.y;        // 0..7

#pragma unroll
    for (int i = 0; i < 32; i += 8) {
        int d = d0 + y + i;
        int t = t0 + x;
        if (t < VOCAB)  // d < DIM guaranteed (DIM % 32 == 0)
            tile[y + i][x] = W[(size_t)d * VOCAB + t];
    }
    __syncthreads();
#pragma unroll
    for (int i = 0; i < 32; i += 8) {
        int t = t0 + y + i;
        int d = d0 + x;
        if (t < VOCAB)
            g_Wt[(size_t)t * DIM + d] = __float2half_rn(tile[x][y + i]);
    }
}

// ---------------------------------------------------------------------------
// Main kernel: one CTA per document row.  (R3 structure; score/tok broadcast
// moved from smem LDS to register-resident __shfl_sync.)
// ---------------------------------------------------------------------------
// smem layout (u32 words): hist[15000] | redbuf[768] | score[512] | tok[512] | warpsum[16]
#define SMEM_WORDS (HWORDS + DIM + SEQL + SEQL + 16)
#define SMEM_BYTES (SMEM_WORDS * 4)

__global__ __launch_bounds__(512, 3)
void bm25_kernel(const int* __restrict__ ids,
                 const int* __restrict__ mask,
                 float* __restrict__ out) {
    extern __shared__ unsigned int sm[];
    unsigned int* hist    = sm;                              // HWORDS
    float*        redbuf  = (float*)(sm + HWORDS);           // DIM
    float*        score   = redbuf + DIM;                    // SEQL
    int*          tokarr  = (int*)(score + SEQL);            // SEQL
    float*        warpsum = (float*)(tokarr + SEQL);         // 16

    const int tid = threadIdx.x;
    const int b   = blockIdx.x;

    // ---- Phase 1: load token, validity ----
    int id = ids [(size_t)b * SEQL + tid];
    int mk = mask[(size_t)b * SEQL + tid];
    bool valid = (mk == 1) && (id > 100) && (id < VOCAB);
    int  t = valid ? id : 0;

    // zero histogram + reduction buffer (completes before the barrier below)
#pragma unroll
    for (int i = tid; i < HWORDS; i += 512) hist[i] = 0u;
    for (int i = tid; i < DIM;    i += 512) redbuf[i] = 0.0f;

    int doc_len = __syncthreads_count(valid);   // barrier + valid count

    // ---- Phase 2: histogram (tf with multiplicity) ----
    const unsigned sh = ((unsigned)t & 1u) << 4;
    if (valid) atomicAdd(&hist[t >> 1], 1u << sh);
    __syncthreads();

    // ---- Phase 3: dedup + score ----
    float length_norm = fmaxf(1.0f + 0.75f * ((float)doc_len * 0.01f - 1.0f), 0.5f);
    float s = 0.0f;
    if (valid) {
        unsigned old = atomicAnd(&hist[t >> 1], ~(0xFFFFu << sh));
        unsigned cnt = (old >> sh) & 0xFFFFu;
        if (cnt) {
            float tf = (float)cnt;
            s = tf * 2.2f / (tf + 1.2f * length_norm);   // (K1+1)=2.2, K1=1.2
        }
    }
    // group-major layout: token tid -> slot (tid&3)*128 + (tid>>2), so each
    // gather group's 128 (score, tok) pairs are contiguous for coalesced LDS
    {
        int slot = (tid & 3) * 128 + (tid >> 2);
        score[slot]  = s;
        tokarr[slot] = t;
    }
    __syncthreads();

    // ---- Phase 4: gather-accumulate (fp16 weights, fp32 accum) ----
    // 4 token groups x 128 lanes. Lane l owns dims {2l,2l+1, 256+2l,256+2l+1,
    // 512+2l,512+2l+1} -> every LDG.32 is a fully-coalesced warp access.
    // Each warp keeps 32 (score, tok) pairs in registers per chunk and
    // broadcasts via __shfl_sync (no smem on the gather critical path).
    const int group = tid >> 7;        // 0..3
    const int lane  = tid & 127;       // 0..127
    const int wl    = tid & 31;        // lane within warp
    const __half2* __restrict__ Wt2 = (const __half2*)g_Wt;
    const float* gscore = score  + group * 128;
    const int*   gtok   = tokarr + group * 128;

    float a0x = 0.f, a0y = 0.f, a1x = 0.f, a1y = 0.f, a2x = 0.f, a2y = 0.f;
    for (int chunk = 0; chunk < 4; chunk++) {
        float myscore = gscore[chunk * 32 + wl];   // coalesced LDS.32
        int   mytok   = gtok  [chunk * 32 + wl];   // coalesced LDS.32
#pragma unroll 4
        for (int k = 0; k < 32; k++) {
            float sj = __shfl_sync(0xFFFFFFFFu, myscore, k);
            int   tj = __shfl_sync(0xFFFFFFFFu, mytok,   k);
            unsigned idx = (unsigned)tj * ROWH2 + lane;
            __half2 h0 = __ldg(&Wt2[idx +   0]);
            __half2 h1 = __ldg(&Wt2[idx + 128]);
            __half2 h2 = __ldg(&Wt2[idx + 256]);
            float2 f0 = __half22float2(h0);
            float2 f1 = __half22float2(h1);
            float2 f2 = __half22float2(h2);
            a0x = fmaf(sj, f0.x, a0x); a0y = fmaf(sj, f0.y, a0y);
            a1x = fmaf(sj, f1.x, a1x); a1y = fmaf(sj, f1.y, a1y);
            a2x = fmaf(sj, f2.x, a2x); a2y = fmaf(sj, f2.y, a2y);
        }
    }
    atomicAdd(&redbuf[      2 * lane    ], a0x);
    atomicAdd(&redbuf[      2 * lane + 1], a0y);
    atomicAdd(&redbuf[256 + 2 * lane    ], a1x);
    atomicAdd(&redbuf[256 + 2 * lane + 1], a1y);
    atomicAdd(&redbuf[512 + 2 * lane    ], a2x);
    atomicAdd(&redbuf[512 + 2 * lane + 1], a2y);
    __syncthreads();

    // ---- Phase 5: normalize + write ----
    float p = 0.0f;
    for (int d = tid; d < DIM; d += 512) { float v = redbuf[d]; p = fmaf(v, v, p); }
#pragma unroll
    for (int o = 16; o; o >>= 1) p += __shfl_xor_sync(0xFFFFFFFFu, p, o);
    if ((tid & 31) == 0) warpsum[tid >> 5] = p;
    __syncthreads();
    if (tid == 0) {
        float ss = 0.0f;
#pragma unroll
        for (int w = 0; w < 16; w++) ss += warpsum[w];
        warpsum[0] = rsqrtf(fmaxf(ss, 1e-30f));
    }
    __syncthreads();
    float rn = warpsum[0];
    for (int d = tid; d < DIM; d += 512)
        out[(size_t)b * DIM + d] = redbuf[d] * rn;
}

// ---------------------------------------------------------------------------
extern "C" void kernel_launch(void* const* d_in, const int* in_sizes, int n_in,
                              void* d_out, int out_size) {
    const int*   ids  = (const int*)d_in[0];
    const int*   mask = (const int*)d_in[1];
    const float* W    = (const float*)d_in[2];
    float*       out  = (float*)d_out;

    int B = in_sizes[0] / SEQL;

    // W -> Wt (transposed, fp16) into the device-global scratch
    dim3 tb(32, 8);
    dim3 tg((VOCAB + 31) / 32, DIM / 32);
    transpose_kernel<<<tg, tb>>>(W);

    cudaFuncSetAttribute(bm25_kernel,
                         cudaFuncAttributeMaxDynamicSharedMemorySize, SMEM_BYTES);
    bm25_kernel<<<B, 512, SMEM_BYTES>>>(ids, mask, out);
}

// round 10
// speedup vs baseline: 1.3061x; 1.2402x over previous
#include <cuda_runtime.h>
#include <cuda_fp16.h>

#define VOCAB 30000
#define DIM   768
#define SEQL  512
#define HWORDS (VOCAB / 2)   // packed 16-bit counts, 2 per u32
#define ROWH2 (DIM / 2)      // 384 half2 per Wt row

// Scratch: transposed weights Wt[VOCAB][DIM] (fp16, 46 MB). Device global
// per the allocation rules (no cudaMalloc anywhere).
__device__ __half g_Wt[(size_t)VOCAB * DIM];

// ---------------------------------------------------------------------------
// Transpose W [DIM, VOCAB] (row-major fp32) -> g_Wt [VOCAB, DIM] (fp16).
// 64-dim x 32-vocab tiles; stores are half2 per lane -> full 128B wavefronts.
// ---------------------------------------------------------------------------
__global__ void transpose_kernel(const float* __restrict__ W) {
    __shared__ float tile[64][33];        // [dim][vocab]
    int t0 = blockIdx.x * 32;             // vocab tile base
    int d0 = blockIdx.y * 64;             // dim tile base
    int x = threadIdx.x;                  // 0..31
    int y = threadIdx.y;                  // 0..7

#pragma unroll
    for (int i = 0; i < 64; i += 8) {
        int d = d0 + y + i;               // < DIM (DIM % 64 == 0)
        int t = t0 + x;
        if (t < VOCAB)
            tile[y + i][x] = W[(size_t)d * VOCAB + t];
    }
    __syncthreads();

    // warp y writes vocab rows t0 + j*8 + y; lane l writes dims (2l, 2l+1)
#pragma unroll
    for (int j = 0; j < 4; j++) {
        int tr = j * 8 + y;               // 0..31 (tile-local vocab row)
        int t  = t0 + tr;
        if (t < VOCAB) {
            __half2 v = __floats2half2_rn(tile[2 * x][tr], tile[2 * x + 1][tr]);
            *(__half2*)&g_Wt[(size_t)t * DIM + d0 + 2 * x] = v;
        }
    }
}

// ---------------------------------------------------------------------------
// Main kernel: one CTA per document row.  (exact R3 structure — the schedule
// that sustains the LTS bandwidth cap.)
//  Phase 1: validity + doc_len (syncthreads_count)
//  Phase 2: packed 16-bit histogram in smem (tf counts)
//  Phase 3: dedup (atomicAnd fetch-and-clear) + BM25 score per unique token
//  Phase 4: token-parallel fp16 gather, fp32 accumulate, smem reduce
//  Phase 5: L2 normalize, write out
// ---------------------------------------------------------------------------
// smem layout (u32 words): hist[15000] | redbuf[768] | score[512] | tok[512] | warpsum[16]
#define SMEM_WORDS (HWORDS + DIM + SEQL + SEQL + 16)
#define SMEM_BYTES (SMEM_WORDS * 4)

__global__ __launch_bounds__(512, 3)
void bm25_kernel(const int* __restrict__ ids,
                 const int* __restrict__ mask,
                 float* __restrict__ out) {
    extern __shared__ unsigned int sm[];
    unsigned int* hist   = sm;                                // HWORDS
    float*        redbuf = (float*)(sm + HWORDS);             // DIM
    float*        score  = redbuf + DIM;                      // SEQL
    int*          tok    = (int*)(score + SEQL);              // SEQL
    float*        warpsum = (float*)(tok + SEQL);             // 16

    const int tid = threadIdx.x;
    const int b   = blockIdx.x;

    // ---- Phase 1: load token, validity ----
    int id = ids [(size_t)b * SEQL + tid];
    int mk = mask[(size_t)b * SEQL + tid];
    bool valid = (mk == 1) && (id > 100) && (id < VOCAB);
    int  t = valid ? id : 0;

    // zero histogram + reduction buffer (completes before the barrier below)
#pragma unroll
    for (int i = tid; i < HWORDS; i += 512) hist[i] = 0u;
    for (int i = tid; i < DIM;    i += 512) redbuf[i] = 0.0f;

    int doc_len = __syncthreads_count(valid);   // barrier + valid count

    // ---- Phase 2: histogram (tf with multiplicity) ----
    const unsigned sh = ((unsigned)t & 1u) << 4;
    if (valid) atomicAdd(&hist[t >> 1], 1u << sh);
    __syncthreads();

    // ---- Phase 3: dedup + score ----
    float length_norm = fmaxf(1.0f + 0.75f * ((float)doc_len * 0.01f - 1.0f), 0.5f);
    float s = 0.0f;
    if (valid) {
        unsigned old = atomicAnd(&hist[t >> 1], ~(0xFFFFu << sh));
        unsigned cnt = (old >> sh) & 0xFFFFu;
        if (cnt) {
            float tf = (float)cnt;
            s = tf * 2.2f / (tf + 1.2f * length_norm);   // (K1+1)=2.2, K1=1.2
        }
    }
    score[tid] = s;   // 0 for invalid tokens and duplicate occurrences
    tok[tid]   = t;   // 0 for invalid (loads Wt row 0, weight 0 -> harmless)
    __syncthreads();

    // ---- Phase 4: gather-accumulate (fp16 weights, fp32 accum) ----
    // 4 token groups x 128 lanes. Lane l owns dims {2l,2l+1, 256+2l,256+2l+1,
    // 512+2l,512+2l+1} -> every LDG.32 is a fully-coalesced warp access.
    const int group = tid >> 7;        // 0..3
    const int lane  = tid & 127;       // 0..127
    const __half2* __restrict__ Wt2 = (const __half2*)g_Wt;

    float a0x = 0.f, a0y = 0.f, a1x = 0.f, a1y = 0.f, a2x = 0.f, a2y = 0.f;
#pragma unroll 4
    for (int j = group; j < SEQL; j += 4) {
        float sj = score[j];
        size_t idx = (size_t)tok[j] * ROWH2 + lane;
        __half2 h0 = __ldg(&Wt2[idx +   0]);
        __half2 h1 = __ldg(&Wt2[idx + 128]);
        __half2 h2 = __ldg(&Wt2[idx + 256]);
        float2 f0 = __half22float2(h0);
        float2 f1 = __half22float2(h1);
        float2 f2 = __half22float2(h2);
        a0x = fmaf(sj, f0.x, a0x); a0y = fmaf(sj, f0.y, a0y);
        a1x = fmaf(sj, f1.x, a1x); a1y = fmaf(sj, f1.y, a1y);
        a2x = fmaf(sj, f2.x, a2x); a2y = fmaf(sj, f2.y, a2y);
    }
    atomicAdd(&redbuf[      2 * lane    ], a0x);
    atomicAdd(&redbuf[      2 * lane + 1], a0y);
    atomicAdd(&redbuf[256 + 2 * lane    ], a1x);
    atomicAdd(&redbuf[256 + 2 * lane + 1], a1y);
    atomicAdd(&redbuf[512 + 2 * lane    ], a2x);
    atomicAdd(&redbuf[512 + 2 * lane + 1], a2y);
    __syncthreads();

    // ---- Phase 5: normalize + write ----
    float p = 0.0f;
    for (int d = tid; d < DIM; d += 512) { float v = redbuf[d]; p = fmaf(v, v, p); }
#pragma unroll
    for (int o = 16; o; o >>= 1) p += __shfl_xor_sync(0xFFFFFFFFu, p, o);
    if ((tid & 31) == 0) warpsum[tid >> 5] = p;
    __syncthreads();
    if (tid == 0) {
        float ss = 0.0f;
#pragma unroll
        for (int w = 0; w < 16; w++) ss += warpsum[w];
        warpsum[0] = rsqrtf(fmaxf(ss, 1e-30f));
    }
    __syncthreads();
    float rn = warpsum[0];
    for (int d = tid; d < DIM; d += 512)
        out[(size_t)b * DIM + d] = redbuf[d] * rn;
}

// ---------------------------------------------------------------------------
extern "C" void kernel_launch(void* const* d_in, const int* in_sizes, int n_in,
                              void* d_out, int out_size) {
    const int*   ids  = (const int*)d_in[0];
    const int*   mask = (const int*)d_in[1];
    const float* W    = (const float*)d_in[2];
    float*       out  = (float*)d_out;

    int B = in_sizes[0] / SEQL;

    // W -> Wt (transposed, fp16) into the device-global scratch
    dim3 tb(32, 8);
    dim3 tg((VOCAB + 31) / 32, DIM / 64);
    transpose_kernel<<<tg, tb>>>(W);

    cudaFuncSetAttribute(bm25_kernel,
                         cudaFuncAttributeMaxDynamicSharedMemorySize, SMEM_BYTES);
    bm25_kernel<<<B, 512, SMEM_BYTES>>>(ids, mask, out);
}

// round 11
// speedup vs baseline: 1.3174x; 1.0086x over previous
#include <cuda_runtime.h>
#include <cuda_fp16.h>

#define VOCAB 30000
#define DIM   768
#define SEQL  512
#define HWORDS (VOCAB / 2)   // packed 16-bit counts, 2 per u32
#define ROWH2 (DIM / 2)      // 384 half2 per Wt row

// Scratch: transposed weights Wt[VOCAB][DIM] (fp16, 46 MB). Device global
// per the allocation rules (no cudaMalloc anywhere).
__device__ __half g_Wt[(size_t)VOCAB * DIM];

// ---------------------------------------------------------------------------
// Transpose W [DIM, VOCAB] (row-major fp32) -> g_Wt [VOCAB, DIM] (fp16).
// 64-dim x 32-vocab tiles; stores are half2 per lane -> full 128B wavefronts.
// ---------------------------------------------------------------------------
__global__ void transpose_kernel(const float* __restrict__ W) {
    __shared__ float tile[64][33];        // [dim][vocab]
    int t0 = blockIdx.x * 32;             // vocab tile base
    int d0 = blockIdx.y * 64;             // dim tile base
    int x = threadIdx.x;                  // 0..31
    int y = threadIdx.y;                  // 0..7

#pragma unroll
    for (int i = 0; i < 64; i += 8) {
        int d = d0 + y + i;               // < DIM (DIM % 64 == 0)
        int t = t0 + x;
        if (t < VOCAB)
            tile[y + i][x] = W[(size_t)d * VOCAB + t];
    }
    __syncthreads();

    // warp y writes vocab rows t0 + j*8 + y; lane l writes dims (2l, 2l+1)
#pragma unroll
    for (int j = 0; j < 4; j++) {
        int tr = j * 8 + y;               // 0..31 (tile-local vocab row)
        int t  = t0 + tr;
        if (t < VOCAB) {
            __half2 v = __floats2half2_rn(tile[2 * x][tr], tile[2 * x + 1][tr]);
            *(__half2*)&g_Wt[(size_t)t * DIM + d0 + 2 * x] = v;
        }
    }
}

// ---------------------------------------------------------------------------
// Main kernel: one CTA per document row.  (exact R3 structure — the schedule
// that sustains the LTS bandwidth cap.)
//  Phase 1: validity + doc_len (syncthreads_count)
//  Phase 2: packed 16-bit histogram in smem (tf counts)
//  Phase 3: dedup (atomicAnd fetch-and-clear) + BM25 score per unique token
//  Phase 4: token-parallel fp16 gather, fp32 accumulate, smem reduce
//  Phase 5: L2 normalize, write out
// ---------------------------------------------------------------------------
// smem layout (u32 words): hist[15000] | redbuf[768] | score[512] | tok[512] | warpsum[16]
#define SMEM_WORDS (HWORDS + DIM + SEQL + SEQL + 16)
#define SMEM_BYTES (SMEM_WORDS * 4)

__global__ __launch_bounds__(512, 3)
void bm25_kernel(const int* __restrict__ ids,
                 const int* __restrict__ mask,
                 float* __restrict__ out) {
    extern __shared__ unsigned int sm[];
    unsigned int* hist   = sm;                                // HWORDS
    float*        redbuf = (float*)(sm + HWORDS);             // DIM
    float*        score  = redbuf + DIM;                      // SEQL
    int*          tok    = (int*)(score + SEQL);              // SEQL
    float*        warpsum = (float*)(tok + SEQL);             // 16

    const int tid = threadIdx.x;
    const int b   = blockIdx.x;

    // ---- Phase 1: load token, validity ----
    int id = ids [(size_t)b * SEQL + tid];
    int mk = mask[(size_t)b * SEQL + tid];
    bool valid = (mk == 1) && (id > 100) && (id < VOCAB);
    int  t = valid ? id : 0;

    // zero histogram + reduction buffer (completes before the barrier below)
#pragma unroll
    for (int i = tid; i < HWORDS; i += 512) hist[i] = 0u;
    for (int i = tid; i < DIM;    i += 512) redbuf[i] = 0.0f;

    int doc_len = __syncthreads_count(valid);   // barrier + valid count

    // ---- Phase 2: histogram (tf with multiplicity) ----
    const unsigned sh = ((unsigned)t & 1u) << 4;
    if (valid) atomicAdd(&hist[t >> 1], 1u << sh);
    __syncthreads();

    // ---- Phase 3: dedup + score ----
    float length_norm = fmaxf(1.0f + 0.75f * ((float)doc_len * 0.01f - 1.0f), 0.5f);
    float s = 0.0f;
    if (valid) {
        unsigned old = atomicAnd(&hist[t >> 1], ~(0xFFFFu << sh));
        unsigned cnt = (old >> sh) & 0xFFFFu;
        if (cnt) {
            float tf = (float)cnt;
            s = tf * 2.2f / (tf + 1.2f * length_norm);   // (K1+1)=2.2, K1=1.2
        }
    }
    score[tid] = s;   // 0 for invalid tokens and duplicate occurrences
    tok[tid]   = t;   // 0 for invalid (loads Wt row 0, weight 0 -> harmless)
    __syncthreads();

    // ---- Phase 4: gather-accumulate (fp16 weights, fp32 accum) ----
    // 4 token groups x 128 lanes. Lane l owns dims {2l,2l+1, 256+2l,256+2l+1,
    // 512+2l,512+2l+1} -> every LDG.32 is a fully-coalesced warp access.
    const int group = tid >> 7;        // 0..3
    const int lane  = tid & 127;       // 0..127
    const __half2* __restrict__ Wt2 = (const __half2*)g_Wt;

    float a0x = 0.f, a0y = 0.f, a1x = 0.f, a1y = 0.f, a2x = 0.f, a2y = 0.f;
#pragma unroll 4
    for (int j = group; j < SEQL; j += 4) {
        float sj = score[j];
        size_t idx = (size_t)tok[j] * ROWH2 + lane;
        __half2 h0 = __ldg(&Wt2[idx +   0]);
        __half2 h1 = __ldg(&Wt2[idx + 128]);
        __half2 h2 = __ldg(&Wt2[idx + 256]);
        float2 f0 = __half22float2(h0);
        float2 f1 = __half22float2(h1);
        float2 f2 = __half22float2(h2);
        a0x = fmaf(sj, f0.x, a0x); a0y = fmaf(sj, f0.y, a0y);
        a1x = fmaf(sj, f1.x, a1x); a1y = fmaf(sj, f1.y, a1y);
        a2x = fmaf(sj, f2.x, a2x); a2y = fmaf(sj, f2.y, a2y);
    }
    atomicAdd(&redbuf[      2 * lane    ], a0x);
    atomicAdd(&redbuf[      2 * lane + 1], a0y);
    atomicAdd(&redbuf[256 + 2 * lane    ], a1x);
    atomicAdd(&redbuf[256 + 2 * lane + 1], a1y);
    atomicAdd(&redbuf[512 + 2 * lane    ], a2x);
    atomicAdd(&redbuf[512 + 2 * lane + 1], a2y);
    __syncthreads();

    // ---- Phase 5: normalize + write ----
    float p = 0.0f;
    for (int d = tid; d < DIM; d += 512) { float v = redbuf[d]; p = fmaf(v, v, p); }
#pragma unroll
    for (int o = 16; o; o >>= 1) p += __shfl_xor_sync(0xFFFFFFFFu, p, o);
    if ((tid & 31) == 0) warpsum[tid >> 5] = p;
    __syncthreads();
    if (tid == 0) {
        float ss = 0.0f;
#pragma unroll
        for (int w = 0; w < 16; w++) ss += warpsum[w];
        warpsum[0] = rsqrtf(fmaxf(ss, 1e-30f));
    }
    __syncthreads();
    float rn = warpsum[0];
    for (int d = tid; d < DIM; d += 512)
        out[(size_t)b * DIM + d] = redbuf[d] * rn;
}

// ---------------------------------------------------------------------------
extern "C" void kernel_launch(void* const* d_in, const int* in_sizes, int n_in,
                              void* d_out, int out_size) {
    const int*   ids  = (const int*)d_in[0];
    const int*   mask = (const int*)d_in[1];
    const float* W    = (const float*)d_in[2];
    float*       out  = (float*)d_out;

    int B = in_sizes[0] / SEQL;

    // W -> Wt (transposed, fp16) into the device-global scratch
    dim3 tb(32, 8);
    dim3 tg((VOCAB + 31) / 32, DIM / 64);
    transpose_kernel<<<tg, tb>>>(W);

    cudaFuncSetAttribute(bm25_kernel,
                         cudaFuncAttributeMaxDynamicSharedMemorySize, SMEM_BYTES);
    bm25_kernel<<<B, 512, SMEM_BYTES>>>(ids, mask, out);
}